// round 1
// baseline (speedup 1.0000x reference)
#include <cuda_runtime.h>

// StackMemory: the reference scan only ever writes stack row 0 and reads row 1,
// which remains zero forever. So:
//   out[0, t, 0, h] = softmax0(hs[t]·W_ap^T + b)[0] * sigmoid(hs[t]·D)   (same for all h)
//   out[0, t, d, h] = 0  for d >= 1
// Kernel: one block per timestep t. Compute the scalar, then stream the
// 32*400-float output row block (100 float4 of val + 3100 float4 of zero).

#define HID 400
#define DEPTH 32
#define THREADS 256

__global__ void __launch_bounds__(THREADS, 8)
stackmem_kernel(const float* __restrict__ hs,
                const float* __restrict__ W,
                const float* __restrict__ b,
                const float* __restrict__ Dv,
                float* __restrict__ out) {
    const int t = blockIdx.x;

    const float4* __restrict__ x4 = reinterpret_cast<const float4*>(hs + (size_t)t * HID);
    const float4* __restrict__ w0 = reinterpret_cast<const float4*>(W);
    const float4* __restrict__ w1 = reinterpret_cast<const float4*>(W + HID);
    const float4* __restrict__ w2 = reinterpret_cast<const float4*>(W + 2 * HID);
    const float4* __restrict__ d4 = reinterpret_cast<const float4*>(Dv);

    float a0 = 0.f, a1 = 0.f, a2 = 0.f, a3 = 0.f;
    // HID/4 = 100 float4 elements; threads 0..99 do one each.
    for (int i = threadIdx.x; i < HID / 4; i += THREADS) {
        float4 x = x4[i];
        float4 p;
        p = w0[i]; a0 += x.x * p.x + x.y * p.y + x.z * p.z + x.w * p.w;
        p = w1[i]; a1 += x.x * p.x + x.y * p.y + x.z * p.z + x.w * p.w;
        p = w2[i]; a2 += x.x * p.x + x.y * p.y + x.z * p.z + x.w * p.w;
        p = d4[i]; a3 += x.x * p.x + x.y * p.y + x.z * p.z + x.w * p.w;
    }

    // Warp reduce
    #pragma unroll
    for (int o = 16; o > 0; o >>= 1) {
        a0 += __shfl_xor_sync(0xFFFFFFFFu, a0, o);
        a1 += __shfl_xor_sync(0xFFFFFFFFu, a1, o);
        a2 += __shfl_xor_sync(0xFFFFFFFFu, a2, o);
        a3 += __shfl_xor_sync(0xFFFFFFFFu, a3, o);
    }

    __shared__ float s[4][THREADS / 32];
    __shared__ float sval;
    const int wid = threadIdx.x >> 5;
    const int lid = threadIdx.x & 31;
    if (lid == 0) {
        s[0][wid] = a0; s[1][wid] = a1; s[2][wid] = a2; s[3][wid] = a3;
    }
    __syncthreads();
    if (threadIdx.x == 0) {
        float l0 = 0.f, l1 = 0.f, l2 = 0.f, l3 = 0.f;
        #pragma unroll
        for (int i = 0; i < THREADS / 32; i++) {
            l0 += s[0][i]; l1 += s[1][i]; l2 += s[2][i]; l3 += s[3][i];
        }
        l0 += b[0]; l1 += b[1]; l2 += b[2];
        float m = fmaxf(l0, fmaxf(l1, l2));
        float e0 = __expf(l0 - m);
        float e1 = __expf(l1 - m);
        float e2 = __expf(l2 - m);
        float p0 = e0 / (e0 + e1 + e2);
        float pv = 1.0f / (1.0f + __expf(-l3));
        sval = p0 * pv;
    }
    __syncthreads();

    const float v = sval;
    const float4 vv = make_float4(v, v, v, v);
    const float4 zz = make_float4(0.f, 0.f, 0.f, 0.f);

    float4* __restrict__ o4 =
        reinterpret_cast<float4*>(out + (size_t)t * DEPTH * HID);
    const int n4 = DEPTH * HID / 4;  // 3200 float4 per timestep
    #pragma unroll 4
    for (int i = threadIdx.x; i < n4; i += THREADS) {
        o4[i] = (i < HID / 4) ? vv : zz;
    }
}

extern "C" void kernel_launch(void* const* d_in, const int* in_sizes, int n_in,
                              void* d_out, int out_size) {
    const float* hs = (const float*)d_in[0];   // (1, T, 400)
    const float* W  = (const float*)d_in[1];   // (3, 400)
    const float* b  = (const float*)d_in[2];   // (3,)
    const float* Dv = (const float*)d_in[3];   // (1, 400)
    float* out = (float*)d_out;                // (1, T, 32, 400)

    const int T = in_sizes[0] / HID;           // B=1
    stackmem_kernel<<<T, THREADS>>>(hs, W, b, Dv, out);
}

// round 2
// speedup vs baseline: 1.0984x; 1.0984x over previous
#include <cuda_runtime.h>

// StackMemory: reference scan only writes stack row 0 and reads row 1 (always
// zero), so:
//   out[0, t, 0, h] = softmax0(hs[t]·W^T + b) * sigmoid(hs[t]·D)  (all h equal)
//   out[0, t, d, h] = 0 for d >= 1
//
// One launch, two block roles:
//   blocks [0, T/32): compute. warp-per-t (4 t per warp), butterfly reduce,
//                     writes the 100-float4 val row for each t. ~26 MB traffic.
//   blocks [T/32, T/32+T): pure streaming zero-fill of the d>=1 region
//                     (3100 float4 per t, 406 MB total). No loads, no barriers.

#define HID    400
#define DEPTH  32
#define ROW4   (DEPTH * HID / 4)   // 3200 float4 per timestep
#define VAL4   (HID / 4)           // 100 float4 val row
#define TPB    256

__global__ void __launch_bounds__(TPB, 8)
stackmem_kernel(const float* __restrict__ hs,
                const float* __restrict__ W,
                const float* __restrict__ b,
                const float* __restrict__ Dv,
                float* __restrict__ out,
                int n_compute_blocks) {
    if ((int)blockIdx.x >= n_compute_blocks) {
        // ---------- pure zero-fill role ----------
        const int t = blockIdx.x - n_compute_blocks;
        float4* __restrict__ o4 =
            reinterpret_cast<float4*>(out + (size_t)t * (DEPTH * HID)) + VAL4;
        const float4 zz = make_float4(0.f, 0.f, 0.f, 0.f);
        // 3100 float4, 256 threads -> 12 full iters + partial
        #pragma unroll 4
        for (int i = threadIdx.x; i < ROW4 - VAL4; i += TPB) {
            __stcs(&o4[i], zz);
        }
        return;
    }

    // ---------- compute role: warp per t, 4 t per warp ----------
    const int wid  = threadIdx.x >> 5;
    const int lane = threadIdx.x & 31;
    const int t0   = blockIdx.x * 32 + wid * 4;

    const float4* __restrict__ w0 = reinterpret_cast<const float4*>(W);
    const float4* __restrict__ w1 = reinterpret_cast<const float4*>(W + HID);
    const float4* __restrict__ w2 = reinterpret_cast<const float4*>(W + 2 * HID);
    const float4* __restrict__ d4 = reinterpret_cast<const float4*>(Dv);
    const float b0 = __ldg(&b[0]), b1 = __ldg(&b[1]), b2 = __ldg(&b[2]);

    #pragma unroll
    for (int k = 0; k < 4; k++) {
        const int t = t0 + k;
        const float4* __restrict__ x4 =
            reinterpret_cast<const float4*>(hs + (size_t)t * HID);

        float a0 = 0.f, a1 = 0.f, a2 = 0.f, a3 = 0.f;
        for (int i = lane; i < VAL4; i += 32) {
            float4 x = __ldg(&x4[i]);
            float4 p;
            p = __ldg(&w0[i]); a0 += x.x*p.x + x.y*p.y + x.z*p.z + x.w*p.w;
            p = __ldg(&w1[i]); a1 += x.x*p.x + x.y*p.y + x.z*p.z + x.w*p.w;
            p = __ldg(&w2[i]); a2 += x.x*p.x + x.y*p.y + x.z*p.z + x.w*p.w;
            p = __ldg(&d4[i]); a3 += x.x*p.x + x.y*p.y + x.z*p.z + x.w*p.w;
        }

        // Butterfly reduce: every lane ends with the full sum (no broadcast).
        #pragma unroll
        for (int o = 16; o > 0; o >>= 1) {
            a0 += __shfl_xor_sync(0xFFFFFFFFu, a0, o);
            a1 += __shfl_xor_sync(0xFFFFFFFFu, a1, o);
            a2 += __shfl_xor_sync(0xFFFFFFFFu, a2, o);
            a3 += __shfl_xor_sync(0xFFFFFFFFu, a3, o);
        }

        const float l0 = a0 + b0, l1 = a1 + b1, l2 = a2 + b2;
        const float m  = fmaxf(l0, fmaxf(l1, l2));
        const float e0 = __expf(l0 - m);
        const float e1 = __expf(l1 - m);
        const float e2 = __expf(l2 - m);
        const float p0 = e0 / (e0 + e1 + e2);
        const float pv = 1.0f / (1.0f + __expf(-a3));
        const float v  = p0 * pv;
        const float4 vv = make_float4(v, v, v, v);

        float4* __restrict__ o4 =
            reinterpret_cast<float4*>(out + (size_t)t * (DEPTH * HID));
        for (int i = lane; i < VAL4; i += 32) {
            __stcs(&o4[i], vv);
        }
    }
}

extern "C" void kernel_launch(void* const* d_in, const int* in_sizes, int n_in,
                              void* d_out, int out_size) {
    const float* hs = (const float*)d_in[0];   // (1, T, 400)
    const float* W  = (const float*)d_in[1];   // (3, 400)
    const float* b  = (const float*)d_in[2];   // (3,)
    const float* Dv = (const float*)d_in[3];   // (1, 400)
    float* out = (float*)d_out;                // (1, T, 32, 400)

    const int T = in_sizes[0] / HID;           // 8192 (B=1)
    const int n_compute = T / 32;              // 256 compute blocks (warp x4 t)
    stackmem_kernel<<<n_compute + T, TPB>>>(hs, W, b, Dv, out, n_compute);
}